// round 15
// baseline (speedup 1.0000x reference)
#include <cuda_runtime.h>
#include <cuda_fp16.h>
#include <cstdint>

// ---------------------------------------------------------------------------
// out (32,4096,512) f32, hidden (2,32,512), W (512,512), b(512), v(512)
// Output = [context (32*512) | attn (32*4096)] f32.
//
// R15: R14 with race-free async choreography. Rule: commit at round head,
// wait_group 0 at round tail, barrier at next round head publishes. Phase 1
// (rounds 0-7): CTA-wide (A staging + convert). Phase 2 (rounds 8-15): A
// resident, W group-private and group-loaded -> per-group named barriers.
// ---------------------------------------------------------------------------
#define B_DIM   32
#define S_DIM   4096
#define H_DIM   512
#define ROWS    128
#define NTILES  1024
#define SLICE_B 16384
#define NT      512

// SMEM layout (bytes)
#define SM_A     0                  // 128 x 1024B fp16 rows (swizzled)
#define SM_RING  131072             // 4 x 16384 (slots 0-1 grp0, 2-3 grp1)
#define SM_STAGE 196608             // 32KB f32 A-band staging
#define SM_SC2   131072             // scratch reusing ring after mainloop
#define SM_SW2   133120             // 128 f32 softmax weights
#define SM_RED   133632             // 16 f32
#define SM_CP    133760             // 512 f32 context-partial merge
#define SM_TOTAL 229376

#define SWZ(byte_in_row, row) ((byte_in_row) ^ (((row) & 7) << 4))

// -------------------- device-global scratch --------------------------------
__device__ __align__(16) unsigned char g_W16[H_DIM * H_DIM * 2];
__device__ float g_bias[B_DIM * H_DIM];
__device__ float g_scores[B_DIM * S_DIM];
__device__ float g_pm[NTILES];
__device__ float g_pl[NTILES];
__device__ float g_pc[NTILES * H_DIM];

// -------------------- helpers ----------------------------------------------
__device__ __forceinline__ uint32_t smem_u32(const void* p) {
    uint32_t a;
    asm("{ .reg .u64 t; cvta.to.shared.u64 t, %1; cvt.u32.u64 %0, t; }"
        : "=r"(a) : "l"(p));
    return a;
}
__device__ __forceinline__ void cp_async16(uint32_t dst, const void* src) {
    asm volatile("cp.async.cg.shared.global [%0], [%1], 16;"
                 :: "r"(dst), "l"(__cvta_generic_to_global(src)) : "memory");
}
#define CP_COMMIT() asm volatile("cp.async.commit_group;" ::: "memory")
#define CP_WAIT0()  asm volatile("cp.async.wait_group 0;" ::: "memory")
#define BAR_GRP(ID) asm volatile("bar.sync %0, 256;" :: "r"(ID) : "memory")

#define LDSM_X4(r0, r1, r2, r3, addr)                                          \
    asm volatile("ldmatrix.sync.aligned.m8n8.x4.shared.b16 {%0,%1,%2,%3}, [%4];" \
                 : "=r"(r0), "=r"(r1), "=r"(r2), "=r"(r3) : "r"(addr))

#define MMA16816(c0, c1, c2, c3, a0, a1, a2, a3, b0, b1)                       \
    asm volatile("mma.sync.aligned.m16n8k16.row.col.f32.f16.f16.f32 "          \
                 "{%0,%1,%2,%3}, {%4,%5,%6,%7}, {%8,%9}, {%0,%1,%2,%3};"       \
                 : "+f"(c0), "+f"(c1), "+f"(c2), "+f"(c3)                      \
                 : "r"(a0), "r"(a1), "r"(a2), "r"(a3), "r"(b0), "r"(b1))

__device__ __forceinline__ float tanh_fast(float x) {
    float e = __expf(2.0f * x);
    return 1.0f - __fdividef(2.0f, e + 1.0f);
}

// ---------------------------------------------------------------------------
// Kernel 0: prep — W f32 -> fp16 slice-major (slice g = (n>>7)*8 + (k>>6):
// 128 N-rows x 64 K-cols, 128B rows, SW128); bias = b + hidden[-1].
// ---------------------------------------------------------------------------
__global__ void prep_kernel(const float* __restrict__ W,
                            const float* __restrict__ bvec,
                            const float* __restrict__ hidden,
                            int hid_off) {
    int idx = blockIdx.x * blockDim.x + threadIdx.x;
    int stride = gridDim.x * blockDim.x;
    for (int i = idx; i < H_DIM * H_DIM; i += stride) {
        int n = i >> 9, k = i & 511;
        int g = (n >> 7) * 8 + (k >> 6);
        uint32_t off = (uint32_t)g * SLICE_B + (uint32_t)(n & 127) * 128u
                     + ((uint32_t)((k & 63) * 2) ^ (((uint32_t)n & 7) << 4));
        *(__half*)(g_W16 + off) = __float2half_rn(W[i]);
    }
    for (int i = idx; i < B_DIM * H_DIM; i += stride)
        g_bias[i] = bvec[i & 511] + hidden[hid_off + i];
}

__global__ void pad_kernel() {}

// ---------------------------------------------------------------------------
// Kernel 1: main
// ---------------------------------------------------------------------------
__global__ void __launch_bounds__(NT, 1)
attn_main_kernel(const float* __restrict__ gout, const float* __restrict__ gv) {
    extern __shared__ char smem[];
    const uint32_t sb = smem_u32(smem);
    const int tid = threadIdx.x;
    const int wid = tid >> 5;
    const int lane = tid & 31;
    const int wg = wid >> 3;         // group 0/1 -> chunks 2g..2g+1
    const int gtid = tid & 255;      // tid within group
    const int wm = wid & 3;          // M warp row: rows wm*32..+31
    const int wnl = (wid >> 2) & 1;  // N warp col within group
    const int tile = blockIdx.x;
    const int bi = tile >> 5;
    const int ti = tile & 31;

    const float4* src4 =
        (const float4*)(gout + (size_t)(bi * S_DIM + ti * ROWS) * H_DIM);

#define STAGE_BAND(S) do {                                                     \
        const int _s = (S);                                                    \
        _Pragma("unroll")                                                      \
        for (int i = 0; i < 4; i++) {                                          \
            int j = tid + i * NT;                                              \
            int r = j >> 4, c4 = j & 15;                                       \
            cp_async16(sb + SM_STAGE + (uint32_t)j * 16u,                      \
                       src4 + (r * 128 + _s * 16 + c4));                       \
        }                                                                      \
    } while (0)

#define CONVERT_BAND(S) do {                                                   \
        const int _s = (S);                                                    \
        _Pragma("unroll")                                                      \
        for (int i = 0; i < 4; i++) {                                          \
            int j = tid + i * NT;                                              \
            int r = j >> 4, c4 = j & 15;                                       \
            float4 f = *(const float4*)(smem + SM_STAGE + (size_t)j * 16);     \
            __half2 h01 = __floats2half2_rn(f.x, f.y);                         \
            __half2 h23 = __floats2half2_rn(f.z, f.w);                         \
            uint2 val;                                                         \
            val.x = *reinterpret_cast<uint32_t*>(&h01);                        \
            val.y = *reinterpret_cast<uint32_t*>(&h23);                        \
            uint32_t off = (uint32_t)r * 1024u +                               \
                SWZ((uint32_t)(_s * 128 + c4 * 8), r);                         \
            *(uint2*)(smem + SM_A + off) = val;                                \
        }                                                                      \
    } while (0)

    // ---- prologue: stage band 0 + W(0) both groups; wait; convert 0 -------
    STAGE_BAND(0);
#pragma unroll
    for (int q = 0; q < 2; q++) {
        uint32_t dst = sb + SM_RING + (q * 2) * SLICE_B + tid * 32;
        const unsigned char* s = g_W16 + (size_t)(q * 16) * SLICE_B + tid * 32;
        cp_async16(dst, s);
        cp_async16(dst + 16, s + 16);
    }
    CP_COMMIT();
    CP_WAIT0();
    CONVERT_BAND(0);

    // ---- ldmatrix lane addressing ----
    const int a_ln = (lane & 7) + ((lane >> 3) & 1) * 8;
    const uint32_t a_sw  = (a_ln & 7) << 4;
    const uint32_t a_t16 = (lane >> 4) * 16;
    const uint32_t a_base0 = sb + SM_A + (wm * 32 + a_ln) * 1024;

    const int b_ln = (lane & 7) + ((lane >> 4) & 1) * 8;
    const uint32_t b_sw  = (b_ln & 7) << 4;
    const uint32_t b_t16 = ((lane >> 3) & 1) * 16;
    const uint32_t b_roff = (uint32_t)(wnl * 64 + b_ln) * 128u;

    float ca[2][8][4];
#pragma unroll
    for (int mi = 0; mi < 2; mi++)
#pragma unroll
        for (int j = 0; j < 8; j++)
#pragma unroll
            for (int q = 0; q < 4; q++) ca[mi][j][q] = 0.f;
    float sc[2][2] = {{0.f, 0.f}, {0.f, 0.f}};

    const float* gbias = g_bias + bi * H_DIM;

#define MMA_BODY(T) do {                                                       \
        const uint32_t wb =                                                    \
            sb + SM_RING + (wg * 2 + ((T) & 1)) * SLICE_B + b_roff;            \
        const uint32_t kbase = (uint32_t)((T) & 7) * 128u;                     \
        _Pragma("unroll")                                                      \
        for (int ks = 0; ks < 4; ks++) {                                       \
            const uint32_t k2w = (uint32_t)ks * 32u;                           \
            uint32_t a0[4], a1[4], b0[4], b1[4], b2[4], b3[4];                 \
            const uint32_t akk = ((kbase + k2w) | a_t16) ^ a_sw;               \
            LDSM_X4(a0[0], a0[1], a0[2], a0[3], a_base0 + akk);                \
            LDSM_X4(a1[0], a1[1], a1[2], a1[3], a_base0 + 16 * 1024 + akk);    \
            const uint32_t bkk = (k2w | b_t16) ^ b_sw;                         \
            LDSM_X4(b0[0], b0[1], b0[2], b0[3], wb + bkk);                     \
            LDSM_X4(b1[0], b1[1], b1[2], b1[3], wb + 16 * 128 + bkk);          \
            LDSM_X4(b2[0], b2[1], b2[2], b2[3], wb + 32 * 128 + bkk);          \
            LDSM_X4(b3[0], b3[1], b3[2], b3[3], wb + 48 * 128 + bkk);          \
            _Pragma("unroll")                                                  \
            for (int mi = 0; mi < 2; mi++) {                                   \
                uint32_t* AR = mi ? a1 : a0;                                   \
                MMA16816(ca[mi][0][0], ca[mi][0][1], ca[mi][0][2],             \
                         ca[mi][0][3], AR[0], AR[1], AR[2], AR[3],             \
                         b0[0], b0[1]);                                        \
                MMA16816(ca[mi][1][0], ca[mi][1][1], ca[mi][1][2],             \
                         ca[mi][1][3], AR[0], AR[1], AR[2], AR[3],             \
                         b0[2], b0[3]);                                        \
                MMA16816(ca[mi][2][0], ca[mi][2][1], ca[mi][2][2],             \
                         ca[mi][2][3], AR[0], AR[1], AR[2], AR[3],             \
                         b1[0], b1[1]);                                        \
                MMA16816(ca[mi][3][0], ca[mi][3][1], ca[mi][3][2],             \
                         ca[mi][3][3], AR[0], AR[1], AR[2], AR[3],             \
                         b1[2], b1[3]);                                        \
                MMA16816(ca[mi][4][0], ca[mi][4][1], ca[mi][4][2],             \
                         ca[mi][4][3], AR[0], AR[1], AR[2], AR[3],             \
                         b2[0], b2[1]);                                        \
                MMA16816(ca[mi][5][0], ca[mi][5][1], ca[mi][5][2],             \
                         ca[mi][5][3], AR[0], AR[1], AR[2], AR[3],             \
                         b2[2], b2[3]);                                        \
                MMA16816(ca[mi][6][0], ca[mi][6][1], ca[mi][6][2],             \
                         ca[mi][6][3], AR[0], AR[1], AR[2], AR[3],             \
                         b3[0], b3[1]);                                        \
                MMA16816(ca[mi][7][0], ca[mi][7][1], ca[mi][7][2],             \
                         ca[mi][7][3], AR[0], AR[1], AR[2], AR[3],             \
                         b3[2], b3[3]);                                        \
            }                                                                  \
        }                                                                      \
    } while (0)

#define EPILOGUE(CHUNK) do {                                                   \
        const int cb = (CHUNK) * 128 + wnl * 64 + (lane & 3) * 2;              \
        _Pragma("unroll")                                                      \
        for (int j = 0; j < 8; j++) {                                          \
            float2 bb = *(const float2*)(gbias + cb + j * 8);                  \
            float2 vv = *(const float2*)(gv + cb + j * 8);                     \
            _Pragma("unroll")                                                  \
            for (int mi = 0; mi < 2; mi++) {                                   \
                sc[mi][0] += tanh_fast(ca[mi][j][0] + bb.x) * vv.x             \
                           + tanh_fast(ca[mi][j][1] + bb.y) * vv.y;            \
                sc[mi][1] += tanh_fast(ca[mi][j][2] + bb.x) * vv.x             \
                           + tanh_fast(ca[mi][j][3] + bb.y) * vv.y;            \
                ca[mi][j][0] = 0.f; ca[mi][j][1] = 0.f;                        \
                ca[mi][j][2] = 0.f; ca[mi][j][3] = 0.f;                        \
            }                                                                  \
        }                                                                      \
    } while (0)

    // ---- Phase 1: rounds 0..7 (CTA-wide). Commit head, wait tail. ---------
#pragma unroll 1
    for (int t = 0; t < 8; t++) {
        __syncthreads();                // publishes W(t), band t, slot drains

        if (t < 7) STAGE_BAND(t + 1);
        {
#pragma unroll
            for (int q = 0; q < 2; q++) {       // W(t+1), both groups
                int slice = q * 16 + t + 1;
                int slot  = q * 2 + ((t + 1) & 1);
                uint32_t dst = sb + SM_RING + slot * SLICE_B + tid * 32;
                const unsigned char* s =
                    g_W16 + (size_t)slice * SLICE_B + tid * 32;
                cp_async16(dst, s);
                cp_async16(dst + 16, s + 16);
            }
        }
        CP_COMMIT();

        MMA_BODY(t);                    // reads only published data

        CP_WAIT0();                     // own async copies done before barrier
        if (t < 7) CONVERT_BAND(t + 1);
        if (t == 7) EPILOGUE(wg * 2);
    }

    // ---- transition: publish W(8) (written by ALL 512 threads) ------------
    __syncthreads();

    // ---- Phase 2: rounds 8..15 — group-private W, group barriers ----------
#pragma unroll 1
    for (int t = 8; t < 16; t++) {
        if (t > 8) BAR_GRP(wg + 1);     // publishes own-group W(t)

        if (t + 1 < 16) {               // own-group W(t+1), 256 thr x 64B
            int slot = wg * 2 + ((t + 1) & 1);
            uint32_t dst = sb + SM_RING + slot * SLICE_B + gtid * 64;
            const unsigned char* s =
                g_W16 + (size_t)(wg * 16 + t + 1) * SLICE_B + gtid * 64;
            cp_async16(dst,      s);
            cp_async16(dst + 16, s + 16);
            cp_async16(dst + 32, s + 32);
            cp_async16(dst + 48, s + 48);
        }
        CP_COMMIT();

        MMA_BODY(t);

        CP_WAIT0();                     // own copies done before next barrier
        if (t == 15) EPILOGUE(wg * 2 + 1);
    }

    // ---- ring region becomes scratch ----
    __syncthreads();
    float* sc2 = (float*)(smem + SM_SC2);      // [4][128]: bank wg*2+wnl
    const int bank = wg * 2 + wnl;
#pragma unroll
    for (int mi = 0; mi < 2; mi++)
#pragma unroll
        for (int h = 0; h < 2; h++) {
            float v = sc[mi][h];
            v += __shfl_xor_sync(0xffffffffu, v, 1);
            v += __shfl_xor_sync(0xffffffffu, v, 2);
            if ((lane & 3) == 0)
                sc2[bank * 128 + wm * 32 + mi * 16 + h * 8 + (lane >> 2)] = v;
        }
    __syncthreads();

    // ---- tile-local softmax over 128 rows ----
    float* sred = (float*)(smem + SM_RED);
    float scv = -1e30f;
    if (tid < 128) {
        scv = sc2[tid] + sc2[128 + tid] + sc2[256 + tid] + sc2[384 + tid];
        g_scores[bi * S_DIM + ti * ROWS + tid] = scv;
    }
    float m = scv;
#pragma unroll
    for (int o = 16; o; o >>= 1) m = fmaxf(m, __shfl_xor_sync(0xffffffffu, m, o));
    if (lane == 0 && wid < 4) sred[wid] = m;
    __syncthreads();
    float mt = fmaxf(fmaxf(sred[0], sred[1]), fmaxf(sred[2], sred[3]));

    float w = (tid < 128) ? __expf(scv - mt) : 0.f;
    float ls = w;
#pragma unroll
    for (int o = 16; o; o >>= 1) ls += __shfl_xor_sync(0xffffffffu, ls, o);
    if (lane == 0 && wid < 4) sred[8 + wid] = ls;
    if (tid < 128) ((float*)(smem + SM_SW2))[tid] = w;
    __syncthreads();
    float lt = sred[8] + sred[9] + sred[10] + sred[11];
    if (tid == 0) { g_pm[tile] = mt; g_pl[tile] = lt; }

    // ---- partial context: 256 col-pairs x 2 row-halves ----
    {
        const float* sw = (const float*)(smem + SM_SW2);
        float* cpart = (float*)(smem + SM_CP);
        const int col0 = (tid & 255) * 2;
        const int r0 = (tid >> 8) * 64;
        float ax = 0.f, ay = 0.f;
#pragma unroll 4
        for (int s = 0; s < 64; s++) {
            int row = r0 + s;
            float ws = sw[row];
            uint32_t off = (uint32_t)row * 1024u + SWZ((uint32_t)(col0 * 2), row);
            __half2 hv = *(const __half2*)(smem + SM_A + off);
            float2 f = __half22float2(hv);
            ax += ws * f.x;
            ay += ws * f.y;
        }
        if (tid >= 256) {
            cpart[(tid - 256) * 2]     = ax;
            cpart[(tid - 256) * 2 + 1] = ay;
        }
        __syncthreads();
        if (tid < 256) {
            ax += cpart[tid * 2];
            ay += cpart[tid * 2 + 1];
            g_pc[(size_t)tile * H_DIM + col0]     = ax;
            g_pc[(size_t)tile * H_DIM + col0 + 1] = ay;
        }
    }
}

// ---------------------------------------------------------------------------
// Kernel 2: finalize — merge 32 tile partials per batch.
// ---------------------------------------------------------------------------
__global__ void finalize_kernel(float* __restrict__ dout) {
    const int bi = blockIdx.x;
    const int tid = threadIdx.x;

    float M = -1e30f;
#pragma unroll
    for (int t = 0; t < 32; t++) M = fmaxf(M, g_pm[bi * 32 + t]);
    float L = 0.f;
#pragma unroll
    for (int t = 0; t < 32; t++)
        L += g_pl[bi * 32 + t] * __expf(g_pm[bi * 32 + t] - M);
    const float invL = 1.0f / L;

    for (int h = tid; h < H_DIM; h += 256) {
        float acc = 0.f;
#pragma unroll
        for (int t = 0; t < 32; t++)
            acc += __expf(g_pm[bi * 32 + t] - M) *
                   g_pc[(size_t)(bi * 32 + t) * H_DIM + h];
        dout[bi * H_DIM + h] = acc * invL;
    }
    for (int s = tid; s < S_DIM; s += 256)
        dout[B_DIM * H_DIM + bi * S_DIM + s] =
            __expf(g_scores[bi * S_DIM + s] - M) * invL;
}

// ---------------------------------------------------------------------------
extern "C" void kernel_launch(void* const* d_in, const int* in_sizes, int n_in,
                              void* d_out, int out_size) {
    const float* out_t  = (const float*)d_in[0];
    const float* hidden = (const float*)d_in[1];
    const float* W      = (const float*)d_in[2];
    const float* bvec   = (const float*)d_in[3];
    const float* v      = (const float*)d_in[4];
    int hid_off = in_sizes[1] - B_DIM * H_DIM;

    cudaFuncSetAttribute(attn_main_kernel,
                         cudaFuncAttributeMaxDynamicSharedMemorySize, SM_TOTAL);

    prep_kernel<<<256, 256>>>(W, bvec, hidden, hid_off);
    pad_kernel<<<1, 32>>>();
    pad_kernel<<<1, 32>>>();
    attn_main_kernel<<<NTILES, NT, SM_TOTAL>>>(out_t, v);
    finalize_kernel<<<B_DIM, 256>>>((float*)d_out);
}

// round 16
// speedup vs baseline: 1.0326x; 1.0326x over previous
#include <cuda_runtime.h>
#include <cuda_fp16.h>
#include <cstdint>

// ---------------------------------------------------------------------------
// out (32,4096,512) f32, hidden (2,32,512), W (512,512), b(512), v(512)
// Output = [context (32*512) | attn (32*4096)] f32.
//
// R16: R15 (race-free dual-group) + B-fragment 2-deep register double-buffer
// in the inner loop (MMA(ks) overlaps LDSM B(ks+1)) + wider prep/finalize.
// ---------------------------------------------------------------------------
#define B_DIM   32
#define S_DIM   4096
#define H_DIM   512
#define ROWS    128
#define NTILES  1024
#define SLICE_B 16384
#define NT      512

// SMEM layout (bytes)
#define SM_A     0                  // 128 x 1024B fp16 rows (swizzled)
#define SM_RING  131072             // 4 x 16384 (slots 0-1 grp0, 2-3 grp1)
#define SM_STAGE 196608             // 32KB f32 A-band staging
#define SM_SC2   131072             // scratch reusing ring after mainloop
#define SM_SW2   133120             // 128 f32 softmax weights
#define SM_RED   133632             // 16 f32
#define SM_CP    133760             // 512 f32 context-partial merge
#define SM_TOTAL 229376

#define SWZ(byte_in_row, row) ((byte_in_row) ^ (((row) & 7) << 4))

// -------------------- device-global scratch --------------------------------
__device__ __align__(16) unsigned char g_W16[H_DIM * H_DIM * 2];
__device__ float g_bias[B_DIM * H_DIM];
__device__ float g_scores[B_DIM * S_DIM];
__device__ float g_pm[NTILES];
__device__ float g_pl[NTILES];
__device__ float g_pc[NTILES * H_DIM];

// -------------------- helpers ----------------------------------------------
__device__ __forceinline__ uint32_t smem_u32(const void* p) {
    uint32_t a;
    asm("{ .reg .u64 t; cvta.to.shared.u64 t, %1; cvt.u32.u64 %0, t; }"
        : "=r"(a) : "l"(p));
    return a;
}
__device__ __forceinline__ void cp_async16(uint32_t dst, const void* src) {
    asm volatile("cp.async.cg.shared.global [%0], [%1], 16;"
                 :: "r"(dst), "l"(__cvta_generic_to_global(src)) : "memory");
}
#define CP_COMMIT() asm volatile("cp.async.commit_group;" ::: "memory")
#define CP_WAIT0()  asm volatile("cp.async.wait_group 0;" ::: "memory")
#define BAR_GRP(ID) asm volatile("bar.sync %0, 256;" :: "r"(ID) : "memory")

#define LDSM_X4(r0, r1, r2, r3, addr)                                          \
    asm volatile("ldmatrix.sync.aligned.m8n8.x4.shared.b16 {%0,%1,%2,%3}, [%4];" \
                 : "=r"(r0), "=r"(r1), "=r"(r2), "=r"(r3) : "r"(addr))

#define MMA16816(c0, c1, c2, c3, a0, a1, a2, a3, b0, b1)                       \
    asm volatile("mma.sync.aligned.m16n8k16.row.col.f32.f16.f16.f32 "          \
                 "{%0,%1,%2,%3}, {%4,%5,%6,%7}, {%8,%9}, {%0,%1,%2,%3};"       \
                 : "+f"(c0), "+f"(c1), "+f"(c2), "+f"(c3)                      \
                 : "r"(a0), "r"(a1), "r"(a2), "r"(a3), "r"(b0), "r"(b1))

__device__ __forceinline__ float tanh_fast(float x) {
    float e = __expf(2.0f * x);
    return 1.0f - __fdividef(2.0f, e + 1.0f);
}

// ---------------------------------------------------------------------------
// Kernel 0: prep — W f32 -> fp16 slice-major (slice g = (n>>7)*8 + (k>>6):
// 128 N-rows x 64 K-cols, 128B rows, SW128); bias = b + hidden[-1].
// ---------------------------------------------------------------------------
__global__ void prep_kernel(const float* __restrict__ W,
                            const float* __restrict__ bvec,
                            const float* __restrict__ hidden,
                            int hid_off) {
    int idx = blockIdx.x * blockDim.x + threadIdx.x;
    int stride = gridDim.x * blockDim.x;
    for (int i = idx; i < H_DIM * H_DIM; i += stride) {
        int n = i >> 9, k = i & 511;
        int g = (n >> 7) * 8 + (k >> 6);
        uint32_t off = (uint32_t)g * SLICE_B + (uint32_t)(n & 127) * 128u
                     + ((uint32_t)((k & 63) * 2) ^ (((uint32_t)n & 7) << 4));
        *(__half*)(g_W16 + off) = __float2half_rn(W[i]);
    }
    for (int i = idx; i < B_DIM * H_DIM; i += stride)
        g_bias[i] = bvec[i & 511] + hidden[hid_off + i];
}

__global__ void pad_kernel() {}

// ---------------------------------------------------------------------------
// Kernel 1: main
// ---------------------------------------------------------------------------
__global__ void __launch_bounds__(NT, 1)
attn_main_kernel(const float* __restrict__ gout, const float* __restrict__ gv) {
    extern __shared__ char smem[];
    const uint32_t sb = smem_u32(smem);
    const int tid = threadIdx.x;
    const int wid = tid >> 5;
    const int lane = tid & 31;
    const int wg = wid >> 3;         // group 0/1 -> chunks 2g..2g+1
    const int gtid = tid & 255;      // tid within group
    const int wm = wid & 3;          // M warp row: rows wm*32..+31
    const int wnl = (wid >> 2) & 1;  // N warp col within group
    const int tile = blockIdx.x;
    const int bi = tile >> 5;
    const int ti = tile & 31;

    const float4* src4 =
        (const float4*)(gout + (size_t)(bi * S_DIM + ti * ROWS) * H_DIM);

#define STAGE_BAND(S) do {                                                     \
        const int _s = (S);                                                    \
        _Pragma("unroll")                                                      \
        for (int i = 0; i < 4; i++) {                                          \
            int j = tid + i * NT;                                              \
            int r = j >> 4, c4 = j & 15;                                       \
            cp_async16(sb + SM_STAGE + (uint32_t)j * 16u,                      \
                       src4 + (r * 128 + _s * 16 + c4));                       \
        }                                                                      \
    } while (0)

#define CONVERT_BAND(S) do {                                                   \
        const int _s = (S);                                                    \
        _Pragma("unroll")                                                      \
        for (int i = 0; i < 4; i++) {                                          \
            int j = tid + i * NT;                                              \
            int r = j >> 4, c4 = j & 15;                                       \
            float4 f = *(const float4*)(smem + SM_STAGE + (size_t)j * 16);     \
            __half2 h01 = __floats2half2_rn(f.x, f.y);                         \
            __half2 h23 = __floats2half2_rn(f.z, f.w);                         \
            uint2 val;                                                         \
            val.x = *reinterpret_cast<uint32_t*>(&h01);                        \
            val.y = *reinterpret_cast<uint32_t*>(&h23);                        \
            uint32_t off = (uint32_t)r * 1024u +                               \
                SWZ((uint32_t)(_s * 128 + c4 * 8), r);                         \
            *(uint2*)(smem + SM_A + off) = val;                                \
        }                                                                      \
    } while (0)

    // ---- prologue: stage band 0 + W(0) both groups; wait; convert 0 -------
    STAGE_BAND(0);
#pragma unroll
    for (int q = 0; q < 2; q++) {
        uint32_t dst = sb + SM_RING + (q * 2) * SLICE_B + tid * 32;
        const unsigned char* s = g_W16 + (size_t)(q * 16) * SLICE_B + tid * 32;
        cp_async16(dst, s);
        cp_async16(dst + 16, s + 16);
    }
    CP_COMMIT();
    CP_WAIT0();
    CONVERT_BAND(0);

    // ---- ldmatrix lane addressing ----
    const int a_ln = (lane & 7) + ((lane >> 3) & 1) * 8;
    const uint32_t a_sw  = (a_ln & 7) << 4;
    const uint32_t a_t16 = (lane >> 4) * 16;
    const uint32_t a_base0 = sb + SM_A + (wm * 32 + a_ln) * 1024;

    const int b_ln = (lane & 7) + ((lane >> 4) & 1) * 8;
    const uint32_t b_sw  = (b_ln & 7) << 4;
    const uint32_t b_t16 = ((lane >> 3) & 1) * 16;
    const uint32_t b_roff = (uint32_t)(wnl * 64 + b_ln) * 128u;

    float ca[2][8][4];
#pragma unroll
    for (int mi = 0; mi < 2; mi++)
#pragma unroll
        for (int j = 0; j < 8; j++)
#pragma unroll
            for (int q = 0; q < 4; q++) ca[mi][j][q] = 0.f;
    float sc[2][2] = {{0.f, 0.f}, {0.f, 0.f}};

    const float* gbias = g_bias + bi * H_DIM;

    // B fragments 2-deep: MMA(ks) overlaps LDSM B(ks+1).
#define LDSM_B(BUF, K2W) do {                                                  \
        const uint32_t _bkk = ((K2W) | b_t16) ^ b_sw;                          \
        LDSM_X4(rb[BUF][0][0], rb[BUF][0][1], rb[BUF][0][2], rb[BUF][0][3],    \
                wb + _bkk);                                                    \
        LDSM_X4(rb[BUF][1][0], rb[BUF][1][1], rb[BUF][1][2], rb[BUF][1][3],    \
                wb + 16 * 128 + _bkk);                                         \
        LDSM_X4(rb[BUF][2][0], rb[BUF][2][1], rb[BUF][2][2], rb[BUF][2][3],    \
                wb + 32 * 128 + _bkk);                                         \
        LDSM_X4(rb[BUF][3][0], rb[BUF][3][1], rb[BUF][3][2], rb[BUF][3][3],    \
                wb + 48 * 128 + _bkk);                                         \
    } while (0)

#define MMA_BODY(T) do {                                                       \
        const uint32_t wb =                                                    \
            sb + SM_RING + (wg * 2 + ((T) & 1)) * SLICE_B + b_roff;            \
        const uint32_t kbase = (uint32_t)((T) & 7) * 128u;                     \
        uint32_t rb[2][4][4];                                                  \
        LDSM_B(0, 0u);                                                         \
        _Pragma("unroll")                                                      \
        for (int ks = 0; ks < 4; ks++) {                                       \
            const int cur = ks & 1;                                            \
            uint32_t a0[4], a1[4];                                             \
            const uint32_t akk = ((kbase + (uint32_t)ks * 32u) | a_t16) ^ a_sw;\
            LDSM_X4(a0[0], a0[1], a0[2], a0[3], a_base0 + akk);                \
            LDSM_X4(a1[0], a1[1], a1[2], a1[3], a_base0 + 16 * 1024 + akk);    \
            if (ks < 3) LDSM_B(cur ^ 1, (uint32_t)(ks + 1) * 32u);             \
            _Pragma("unroll")                                                  \
            for (int mi = 0; mi < 2; mi++) {                                   \
                uint32_t* AR = mi ? a1 : a0;                                   \
                _Pragma("unroll")                                              \
                for (int nj = 0; nj < 8; nj++) {                               \
                    MMA16816(ca[mi][nj][0], ca[mi][nj][1],                     \
                             ca[mi][nj][2], ca[mi][nj][3],                     \
                             AR[0], AR[1], AR[2], AR[3],                       \
                             rb[cur][nj >> 1][(nj & 1) * 2],                   \
                             rb[cur][nj >> 1][(nj & 1) * 2 + 1]);              \
                }                                                              \
            }                                                                  \
        }                                                                      \
    } while (0)

#define EPILOGUE(CHUNK) do {                                                   \
        const int cb = (CHUNK) * 128 + wnl * 64 + (lane & 3) * 2;              \
        _Pragma("unroll")                                                      \
        for (int j = 0; j < 8; j++) {                                          \
            float2 bb = *(const float2*)(gbias + cb + j * 8);                  \
            float2 vv = *(const float2*)(gv + cb + j * 8);                     \
            _Pragma("unroll")                                                  \
            for (int mi = 0; mi < 2; mi++) {                                   \
                sc[mi][0] += tanh_fast(ca[mi][j][0] + bb.x) * vv.x             \
                           + tanh_fast(ca[mi][j][1] + bb.y) * vv.y;            \
                sc[mi][1] += tanh_fast(ca[mi][j][2] + bb.x) * vv.x             \
                           + tanh_fast(ca[mi][j][3] + bb.y) * vv.y;            \
                ca[mi][j][0] = 0.f; ca[mi][j][1] = 0.f;                        \
                ca[mi][j][2] = 0.f; ca[mi][j][3] = 0.f;                        \
            }                                                                  \
        }                                                                      \
    } while (0)

    // ---- Phase 1: rounds 0..7 (CTA-wide). Commit head, wait tail. ---------
#pragma unroll 1
    for (int t = 0; t < 8; t++) {
        __syncthreads();                // publishes W(t), band t, slot drains

        if (t < 7) STAGE_BAND(t + 1);
        {
#pragma unroll
            for (int q = 0; q < 2; q++) {       // W(t+1), both groups
                int slice = q * 16 + t + 1;
                int slot  = q * 2 + ((t + 1) & 1);
                uint32_t dst = sb + SM_RING + slot * SLICE_B + tid * 32;
                const unsigned char* s =
                    g_W16 + (size_t)slice * SLICE_B + tid * 32;
                cp_async16(dst, s);
                cp_async16(dst + 16, s + 16);
            }
        }
        CP_COMMIT();

        MMA_BODY(t);                    // reads only published data

        CP_WAIT0();                     // own async copies done before barrier
        if (t < 7) CONVERT_BAND(t + 1);
        if (t == 7) EPILOGUE(wg * 2);
    }

    // ---- transition: publish W(8) (written by ALL 512 threads) ------------
    __syncthreads();

    // ---- Phase 2: rounds 8..15 — group-private W, group barriers ----------
#pragma unroll 1
    for (int t = 8; t < 16; t++) {
        if (t > 8) BAR_GRP(wg + 1);     // publishes own-group W(t)

        if (t + 1 < 16) {               // own-group W(t+1), 256 thr x 64B
            int slot = wg * 2 + ((t + 1) & 1);
            uint32_t dst = sb + SM_RING + slot * SLICE_B + gtid * 64;
            const unsigned char* s =
                g_W16 + (size_t)(wg * 16 + t + 1) * SLICE_B + gtid * 64;
            cp_async16(dst,      s);
            cp_async16(dst + 16, s + 16);
            cp_async16(dst + 32, s + 32);
            cp_async16(dst + 48, s + 48);
        }
        CP_COMMIT();

        MMA_BODY(t);

        CP_WAIT0();                     // own copies done before next barrier
        if (t == 15) EPILOGUE(wg * 2 + 1);
    }

    // ---- ring region becomes scratch ----
    __syncthreads();
    float* sc2 = (float*)(smem + SM_SC2);      // [4][128]: bank wg*2+wnl
    const int bank = wg * 2 + wnl;
#pragma unroll
    for (int mi = 0; mi < 2; mi++)
#pragma unroll
        for (int h = 0; h < 2; h++) {
            float v = sc[mi][h];
            v += __shfl_xor_sync(0xffffffffu, v, 1);
            v += __shfl_xor_sync(0xffffffffu, v, 2);
            if ((lane & 3) == 0)
                sc2[bank * 128 + wm * 32 + mi * 16 + h * 8 + (lane >> 2)] = v;
        }
    __syncthreads();

    // ---- tile-local softmax over 128 rows ----
    float* sred = (float*)(smem + SM_RED);
    float scv = -1e30f;
    if (tid < 128) {
        scv = sc2[tid] + sc2[128 + tid] + sc2[256 + tid] + sc2[384 + tid];
        g_scores[bi * S_DIM + ti * ROWS + tid] = scv;
    }
    float m = scv;
#pragma unroll
    for (int o = 16; o; o >>= 1) m = fmaxf(m, __shfl_xor_sync(0xffffffffu, m, o));
    if (lane == 0 && wid < 4) sred[wid] = m;
    __syncthreads();
    float mt = fmaxf(fmaxf(sred[0], sred[1]), fmaxf(sred[2], sred[3]));

    float w = (tid < 128) ? __expf(scv - mt) : 0.f;
    float ls = w;
#pragma unroll
    for (int o = 16; o; o >>= 1) ls += __shfl_xor_sync(0xffffffffu, ls, o);
    if (lane == 0 && wid < 4) sred[8 + wid] = ls;
    if (tid < 128) ((float*)(smem + SM_SW2))[tid] = w;
    __syncthreads();
    float lt = sred[8] + sred[9] + sred[10] + sred[11];
    if (tid == 0) { g_pm[tile] = mt; g_pl[tile] = lt; }

    // ---- partial context: 256 col-pairs x 2 row-halves ----
    {
        const float* sw = (const float*)(smem + SM_SW2);
        float* cpart = (float*)(smem + SM_CP);
        const int col0 = (tid & 255) * 2;
        const int r0 = (tid >> 8) * 64;
        float ax = 0.f, ay = 0.f;
#pragma unroll 4
        for (int s = 0; s < 64; s++) {
            int row = r0 + s;
            float ws = sw[row];
            uint32_t off = (uint32_t)row * 1024u + SWZ((uint32_t)(col0 * 2), row);
            __half2 hv = *(const __half2*)(smem + SM_A + off);
            float2 f = __half22float2(hv);
            ax += ws * f.x;
            ay += ws * f.y;
        }
        if (tid >= 256) {
            cpart[(tid - 256) * 2]     = ax;
            cpart[(tid - 256) * 2 + 1] = ay;
        }
        __syncthreads();
        if (tid < 256) {
            ax += cpart[tid * 2];
            ay += cpart[tid * 2 + 1];
            g_pc[(size_t)tile * H_DIM + col0]     = ax;
            g_pc[(size_t)tile * H_DIM + col0 + 1] = ay;
        }
    }
}

// ---------------------------------------------------------------------------
// Kernel 2: finalize — 8 blocks per batch; each computes M/L redundantly
// (32 values) and writes 64 context cols + 512 attn elems.
// ---------------------------------------------------------------------------
__global__ void finalize_kernel(float* __restrict__ dout) {
    const int bi = blockIdx.x >> 3;
    const int part = blockIdx.x & 7;
    const int tid = threadIdx.x;

    float M = -1e30f;
#pragma unroll
    for (int t = 0; t < 32; t++) M = fmaxf(M, g_pm[bi * 32 + t]);
    float L = 0.f;
#pragma unroll
    for (int t = 0; t < 32; t++)
        L += g_pl[bi * 32 + t] * __expf(g_pm[bi * 32 + t] - M);
    const float invL = 1.0f / L;

    if (tid < 64) {
        int h = part * 64 + tid;
        float acc = 0.f;
#pragma unroll
        for (int t = 0; t < 32; t++)
            acc += __expf(g_pm[bi * 32 + t] - M) *
                   g_pc[(size_t)(bi * 32 + t) * H_DIM + h];
        dout[bi * H_DIM + h] = acc * invL;
    }
#pragma unroll
    for (int k = 0; k < 2; k++) {
        int s = part * 512 + k * 256 + tid;
        dout[B_DIM * H_DIM + bi * S_DIM + s] =
            __expf(g_scores[bi * S_DIM + s] - M) * invL;
    }
}

// ---------------------------------------------------------------------------
extern "C" void kernel_launch(void* const* d_in, const int* in_sizes, int n_in,
                              void* d_out, int out_size) {
    const float* out_t  = (const float*)d_in[0];
    const float* hidden = (const float*)d_in[1];
    const float* W      = (const float*)d_in[2];
    const float* bvec   = (const float*)d_in[3];
    const float* v      = (const float*)d_in[4];
    int hid_off = in_sizes[1] - B_DIM * H_DIM;

    cudaFuncSetAttribute(attn_main_kernel,
                         cudaFuncAttributeMaxDynamicSharedMemorySize, SM_TOTAL);

    prep_kernel<<<512, 256>>>(W, bvec, hidden, hid_off);
    pad_kernel<<<1, 32>>>();
    pad_kernel<<<1, 32>>>();
    attn_main_kernel<<<NTILES, NT, SM_TOTAL>>>(out_t, v);
    finalize_kernel<<<B_DIM * 8, 256>>>((float*)d_out);
}

// round 17
// speedup vs baseline: 1.0538x; 1.0206x over previous
#include <cuda_runtime.h>
#include <cuda_fp16.h>
#include <cstdint>

// ---------------------------------------------------------------------------
// out (32,4096,512) f32, hidden (2,32,512), W (512,512), b(512), v(512)
// Output = [context (32*512) | attn (32*4096)] f32.
//
// R17: R16 + LDSM address precomputation. Swizzle algebra is bit-disjoint:
// ((kbase+k2w)|t16)^sw == kbase + ((k2w|t16)^sw), so the 4 A-offsets and
// 4 B-offsets are kernel-invariant registers; each LDSM address is one IADD
// off a per-round base. Cuts scalar issue pressure in the mainloop.
// ---------------------------------------------------------------------------
#define B_DIM   32
#define S_DIM   4096
#define H_DIM   512
#define ROWS    128
#define NTILES  1024
#define SLICE_B 16384
#define NT      512

// SMEM layout (bytes)
#define SM_A     0                  // 128 x 1024B fp16 rows (swizzled)
#define SM_RING  131072             // 4 x 16384 (slots 0-1 grp0, 2-3 grp1)
#define SM_STAGE 196608             // 32KB f32 A-band staging
#define SM_SC2   131072             // scratch reusing ring after mainloop
#define SM_SW2   133120             // 128 f32 softmax weights
#define SM_RED   133632             // 16 f32
#define SM_CP    133760             // 512 f32 context-partial merge
#define SM_TOTAL 229376

#define SWZ(byte_in_row, row) ((byte_in_row) ^ (((row) & 7) << 4))

// -------------------- device-global scratch --------------------------------
__device__ __align__(16) unsigned char g_W16[H_DIM * H_DIM * 2];
__device__ float g_bias[B_DIM * H_DIM];
__device__ float g_scores[B_DIM * S_DIM];
__device__ float g_pm[NTILES];
__device__ float g_pl[NTILES];
__device__ float g_pc[NTILES * H_DIM];

// -------------------- helpers ----------------------------------------------
__device__ __forceinline__ uint32_t smem_u32(const void* p) {
    uint32_t a;
    asm("{ .reg .u64 t; cvta.to.shared.u64 t, %1; cvt.u32.u64 %0, t; }"
        : "=r"(a) : "l"(p));
    return a;
}
__device__ __forceinline__ void cp_async16(uint32_t dst, const void* src) {
    asm volatile("cp.async.cg.shared.global [%0], [%1], 16;"
                 :: "r"(dst), "l"(__cvta_generic_to_global(src)) : "memory");
}
#define CP_COMMIT() asm volatile("cp.async.commit_group;" ::: "memory")
#define CP_WAIT0()  asm volatile("cp.async.wait_group 0;" ::: "memory")
#define BAR_GRP(ID) asm volatile("bar.sync %0, 256;" :: "r"(ID) : "memory")

#define LDSM_X4(r0, r1, r2, r3, addr)                                          \
    asm volatile("ldmatrix.sync.aligned.m8n8.x4.shared.b16 {%0,%1,%2,%3}, [%4];" \
                 : "=r"(r0), "=r"(r1), "=r"(r2), "=r"(r3) : "r"(addr))

#define MMA16816(c0, c1, c2, c3, a0, a1, a2, a3, b0, b1)                       \
    asm volatile("mma.sync.aligned.m16n8k16.row.col.f32.f16.f16.f32 "          \
                 "{%0,%1,%2,%3}, {%4,%5,%6,%7}, {%8,%9}, {%0,%1,%2,%3};"       \
                 : "+f"(c0), "+f"(c1), "+f"(c2), "+f"(c3)                      \
                 : "r"(a0), "r"(a1), "r"(a2), "r"(a3), "r"(b0), "r"(b1))

__device__ __forceinline__ float tanh_fast(float x) {
    float e = __expf(2.0f * x);
    return 1.0f - __fdividef(2.0f, e + 1.0f);
}

// ---------------------------------------------------------------------------
// Kernel 0: prep — W f32 -> fp16 slice-major (slice g = (n>>7)*8 + (k>>6):
// 128 N-rows x 64 K-cols, 128B rows, SW128); bias = b + hidden[-1].
// ---------------------------------------------------------------------------
__global__ void prep_kernel(const float* __restrict__ W,
                            const float* __restrict__ bvec,
                            const float* __restrict__ hidden,
                            int hid_off) {
    int idx = blockIdx.x * blockDim.x + threadIdx.x;
    int stride = gridDim.x * blockDim.x;
    for (int i = idx; i < H_DIM * H_DIM; i += stride) {
        int n = i >> 9, k = i & 511;
        int g = (n >> 7) * 8 + (k >> 6);
        uint32_t off = (uint32_t)g * SLICE_B + (uint32_t)(n & 127) * 128u
                     + ((uint32_t)((k & 63) * 2) ^ (((uint32_t)n & 7) << 4));
        *(__half*)(g_W16 + off) = __float2half_rn(W[i]);
    }
    for (int i = idx; i < B_DIM * H_DIM; i += stride)
        g_bias[i] = bvec[i & 511] + hidden[hid_off + i];
}

__global__ void pad_kernel() {}

// ---------------------------------------------------------------------------
// Kernel 1: main
// ---------------------------------------------------------------------------
__global__ void __launch_bounds__(NT, 1)
attn_main_kernel(const float* __restrict__ gout, const float* __restrict__ gv) {
    extern __shared__ char smem[];
    const uint32_t sb = smem_u32(smem);
    const int tid = threadIdx.x;
    const int wid = tid >> 5;
    const int lane = tid & 31;
    const int wg = wid >> 3;         // group 0/1 -> chunks 2g..2g+1
    const int gtid = tid & 255;      // tid within group
    const int wm = wid & 3;          // M warp row: rows wm*32..+31
    const int wnl = (wid >> 2) & 1;  // N warp col within group
    const int tile = blockIdx.x;
    const int bi = tile >> 5;
    const int ti = tile & 31;

    const float4* src4 =
        (const float4*)(gout + (size_t)(bi * S_DIM + ti * ROWS) * H_DIM);

#define STAGE_BAND(S) do {                                                     \
        const int _s = (S);                                                    \
        _Pragma("unroll")                                                      \
        for (int i = 0; i < 4; i++) {                                          \
            int j = tid + i * NT;                                              \
            int r = j >> 4, c4 = j & 15;                                       \
            cp_async16(sb + SM_STAGE + (uint32_t)j * 16u,                      \
                       src4 + (r * 128 + _s * 16 + c4));                       \
        }                                                                      \
    } while (0)

#define CONVERT_BAND(S) do {                                                   \
        const int _s = (S);                                                    \
        _Pragma("unroll")                                                      \
        for (int i = 0; i < 4; i++) {                                          \
            int j = tid + i * NT;                                              \
            int r = j >> 4, c4 = j & 15;                                       \
            float4 f = *(const float4*)(smem + SM_STAGE + (size_t)j * 16);     \
            __half2 h01 = __floats2half2_rn(f.x, f.y);                         \
            __half2 h23 = __floats2half2_rn(f.z, f.w);                         \
            uint2 val;                                                         \
            val.x = *reinterpret_cast<uint32_t*>(&h01);                        \
            val.y = *reinterpret_cast<uint32_t*>(&h23);                        \
            uint32_t off = (uint32_t)r * 1024u +                               \
                SWZ((uint32_t)(_s * 128 + c4 * 8), r);                         \
            *(uint2*)(smem + SM_A + off) = val;                                \
        }                                                                      \
    } while (0)

    // ---- prologue: stage band 0 + W(0) both groups; wait; convert 0 -------
    STAGE_BAND(0);
#pragma unroll
    for (int q = 0; q < 2; q++) {
        uint32_t dst = sb + SM_RING + (q * 2) * SLICE_B + tid * 32;
        const unsigned char* s = g_W16 + (size_t)(q * 16) * SLICE_B + tid * 32;
        cp_async16(dst, s);
        cp_async16(dst + 16, s + 16);
    }
    CP_COMMIT();
    CP_WAIT0();
    CONVERT_BAND(0);

    // ---- precomputed LDSM offsets (kernel-invariant registers) ------------
    // akk(ks,kbase) = kbase + ((ks*32 | a_t16) ^ a_sw)   (bit-disjoint)
    // bkk(ks)       = (ks*32 | b_t16) ^ b_sw
    const int a_ln = (lane & 7) + ((lane >> 3) & 1) * 8;
    const uint32_t a_sw  = (a_ln & 7) << 4;
    const uint32_t a_t16 = (lane >> 4) * 16;
    const uint32_t a_base0 = sb + SM_A + (wm * 32 + a_ln) * 1024;

    const int b_ln = (lane & 7) + ((lane >> 4) & 1) * 8;
    const uint32_t b_sw  = (b_ln & 7) << 4;
    const uint32_t b_t16 = ((lane >> 3) & 1) * 16;
    const uint32_t b_roff = (uint32_t)(wnl * 64 + b_ln) * 128u;

    uint32_t aoff[4], boff[4];
#pragma unroll
    for (int ks = 0; ks < 4; ks++) {
        aoff[ks] = a_base0 + (((uint32_t)ks * 32u | a_t16) ^ a_sw);
        boff[ks] = b_roff + (((uint32_t)ks * 32u | b_t16) ^ b_sw);
    }

    float ca[2][8][4];
#pragma unroll
    for (int mi = 0; mi < 2; mi++)
#pragma unroll
        for (int j = 0; j < 8; j++)
#pragma unroll
            for (int q = 0; q < 4; q++) ca[mi][j][q] = 0.f;
    float sc[2][2] = {{0.f, 0.f}, {0.f, 0.f}};

    const float* gbias = g_bias + bi * H_DIM;

    // B fragments 2-deep: MMA(ks) overlaps LDSM B(ks+1).
#define LDSM_B(BUF, KS) do {                                                   \
        const uint32_t _b = wb + boff[KS];                                     \
        LDSM_X4(rb[BUF][0][0], rb[BUF][0][1], rb[BUF][0][2], rb[BUF][0][3],    \
                _b);                                                           \
        LDSM_X4(rb[BUF][1][0], rb[BUF][1][1], rb[BUF][1][2], rb[BUF][1][3],    \
                _b + 2048);                                                    \
        LDSM_X4(rb[BUF][2][0], rb[BUF][2][1], rb[BUF][2][2], rb[BUF][2][3],    \
                _b + 4096);                                                    \
        LDSM_X4(rb[BUF][3][0], rb[BUF][3][1], rb[BUF][3][2], rb[BUF][3][3],    \
                _b + 6144);                                                    \
    } while (0)

#define MMA_BODY(T) do {                                                       \
        const uint32_t wb =                                                    \
            sb + SM_RING + (wg * 2 + ((T) & 1)) * SLICE_B;                     \
        const uint32_t kbase = (uint32_t)((T) & 7) * 128u;                     \
        uint32_t rb[2][4][4];                                                  \
        LDSM_B(0, 0);                                                          \
        _Pragma("unroll")                                                      \
        for (int ks = 0; ks < 4; ks++) {                                       \
            const int cur = ks & 1;                                            \
            uint32_t a0[4], a1[4];                                             \
            const uint32_t _a = aoff[ks] + kbase;                              \
            LDSM_X4(a0[0], a0[1], a0[2], a0[3], _a);                           \
            LDSM_X4(a1[0], a1[1], a1[2], a1[3], _a + 16 * 1024);               \
            if (ks < 3) LDSM_B(cur ^ 1, ks + 1);                               \
            _Pragma("unroll")                                                  \
            for (int mi = 0; mi < 2; mi++) {                                   \
                uint32_t* AR = mi ? a1 : a0;                                   \
                _Pragma("unroll")                                              \
                for (int nj = 0; nj < 8; nj++) {                               \
                    MMA16816(ca[mi][nj][0], ca[mi][nj][1],                     \
                             ca[mi][nj][2], ca[mi][nj][3],                     \
                             AR[0], AR[1], AR[2], AR[3],                       \
                             rb[cur][nj >> 1][(nj & 1) * 2],                   \
                             rb[cur][nj >> 1][(nj & 1) * 2 + 1]);              \
                }                                                              \
            }                                                                  \
        }                                                                      \
    } while (0)

#define EPILOGUE(CHUNK) do {                                                   \
        const int cb = (CHUNK) * 128 + wnl * 64 + (lane & 3) * 2;              \
        _Pragma("unroll")                                                      \
        for (int j = 0; j < 8; j++) {                                          \
            float2 bb = *(const float2*)(gbias + cb + j * 8);                  \
            float2 vv = *(const float2*)(gv + cb + j * 8);                     \
            _Pragma("unroll")                                                  \
            for (int mi = 0; mi < 2; mi++) {                                   \
                sc[mi][0] += tanh_fast(ca[mi][j][0] + bb.x) * vv.x             \
                           + tanh_fast(ca[mi][j][1] + bb.y) * vv.y;            \
                sc[mi][1] += tanh_fast(ca[mi][j][2] + bb.x) * vv.x             \
                           + tanh_fast(ca[mi][j][3] + bb.y) * vv.y;            \
                ca[mi][j][0] = 0.f; ca[mi][j][1] = 0.f;                        \
                ca[mi][j][2] = 0.f; ca[mi][j][3] = 0.f;                        \
            }                                                                  \
        }                                                                      \
    } while (0)

    // ---- Phase 1: rounds 0..7 (CTA-wide). Commit head, wait tail. ---------
#pragma unroll 1
    for (int t = 0; t < 8; t++) {
        __syncthreads();                // publishes W(t), band t, slot drains

        if (t < 7) STAGE_BAND(t + 1);
        {
#pragma unroll
            for (int q = 0; q < 2; q++) {       // W(t+1), both groups
                int slice = q * 16 + t + 1;
                int slot  = q * 2 + ((t + 1) & 1);
                uint32_t dst = sb + SM_RING + slot * SLICE_B + tid * 32;
                const unsigned char* s =
                    g_W16 + (size_t)slice * SLICE_B + tid * 32;
                cp_async16(dst, s);
                cp_async16(dst + 16, s + 16);
            }
        }
        CP_COMMIT();

        MMA_BODY(t);                    // reads only published data

        CP_WAIT0();                     // own async copies done before barrier
        if (t < 7) CONVERT_BAND(t + 1);
        if (t == 7) EPILOGUE(wg * 2);
    }

    // ---- transition: publish W(8) (written by ALL 512 threads) ------------
    __syncthreads();

    // ---- Phase 2: rounds 8..15 — group-private W, group barriers ----------
#pragma unroll 1
    for (int t = 8; t < 16; t++) {
        if (t > 8) BAR_GRP(wg + 1);     // publishes own-group W(t)

        if (t + 1 < 16) {               // own-group W(t+1), 256 thr x 64B
            int slot = wg * 2 + ((t + 1) & 1);
            uint32_t dst = sb + SM_RING + slot * SLICE_B + gtid * 64;
            const unsigned char* s =
                g_W16 + (size_t)(wg * 16 + t + 1) * SLICE_B + gtid * 64;
            cp_async16(dst,      s);
            cp_async16(dst + 16, s + 16);
            cp_async16(dst + 32, s + 32);
            cp_async16(dst + 48, s + 48);
        }
        CP_COMMIT();

        MMA_BODY(t);

        CP_WAIT0();                     // own copies done before next barrier
        if (t == 15) EPILOGUE(wg * 2 + 1);
    }

    // ---- ring region becomes scratch ----
    __syncthreads();
    float* sc2 = (float*)(smem + SM_SC2);      // [4][128]: bank wg*2+wnl
    const int bank = wg * 2 + wnl;
#pragma unroll
    for (int mi = 0; mi < 2; mi++)
#pragma unroll
        for (int h = 0; h < 2; h++) {
            float v = sc[mi][h];
            v += __shfl_xor_sync(0xffffffffu, v, 1);
            v += __shfl_xor_sync(0xffffffffu, v, 2);
            if ((lane & 3) == 0)
                sc2[bank * 128 + wm * 32 + mi * 16 + h * 8 + (lane >> 2)] = v;
        }
    __syncthreads();

    // ---- tile-local softmax over 128 rows ----
    float* sred = (float*)(smem + SM_RED);
    float scv = -1e30f;
    if (tid < 128) {
        scv = sc2[tid] + sc2[128 + tid] + sc2[256 + tid] + sc2[384 + tid];
        g_scores[bi * S_DIM + ti * ROWS + tid] = scv;
    }
    float m = scv;
#pragma unroll
    for (int o = 16; o; o >>= 1) m = fmaxf(m, __shfl_xor_sync(0xffffffffu, m, o));
    if (lane == 0 && wid < 4) sred[wid] = m;
    __syncthreads();
    float mt = fmaxf(fmaxf(sred[0], sred[1]), fmaxf(sred[2], sred[3]));

    float w = (tid < 128) ? __expf(scv - mt) : 0.f;
    float ls = w;
#pragma unroll
    for (int o = 16; o; o >>= 1) ls += __shfl_xor_sync(0xffffffffu, ls, o);
    if (lane == 0 && wid < 4) sred[8 + wid] = ls;
    if (tid < 128) ((float*)(smem + SM_SW2))[tid] = w;
    __syncthreads();
    float lt = sred[8] + sred[9] + sred[10] + sred[11];
    if (tid == 0) { g_pm[tile] = mt; g_pl[tile] = lt; }

    // ---- partial context: 256 col-pairs x 2 row-halves ----
    {
        const float* sw = (const float*)(smem + SM_SW2);
        float* cpart = (float*)(smem + SM_CP);
        const int col0 = (tid & 255) * 2;
        const int r0 = (tid >> 8) * 64;
        float ax = 0.f, ay = 0.f;
#pragma unroll 4
        for (int s = 0; s < 64; s++) {
            int row = r0 + s;
            float ws = sw[row];
            uint32_t off = (uint32_t)row * 1024u + SWZ((uint32_t)(col0 * 2), row);
            __half2 hv = *(const __half2*)(smem + SM_A + off);
            float2 f = __half22float2(hv);
            ax += ws * f.x;
            ay += ws * f.y;
        }
        if (tid >= 256) {
            cpart[(tid - 256) * 2]     = ax;
            cpart[(tid - 256) * 2 + 1] = ay;
        }
        __syncthreads();
        if (tid < 256) {
            ax += cpart[tid * 2];
            ay += cpart[tid * 2 + 1];
            g_pc[(size_t)tile * H_DIM + col0]     = ax;
            g_pc[(size_t)tile * H_DIM + col0 + 1] = ay;
        }
    }
}

// ---------------------------------------------------------------------------
// Kernel 2: finalize — 8 blocks per batch; M/L computed redundantly.
// ---------------------------------------------------------------------------
__global__ void finalize_kernel(float* __restrict__ dout) {
    const int bi = blockIdx.x >> 3;
    const int part = blockIdx.x & 7;
    const int tid = threadIdx.x;

    float M = -1e30f;
#pragma unroll
    for (int t = 0; t < 32; t++) M = fmaxf(M, g_pm[bi * 32 + t]);
    float L = 0.f;
#pragma unroll
    for (int t = 0; t < 32; t++)
        L += g_pl[bi * 32 + t] * __expf(g_pm[bi * 32 + t] - M);
    const float invL = 1.0f / L;

    if (tid < 64) {
        int h = part * 64 + tid;
        float acc = 0.f;
#pragma unroll
        for (int t = 0; t < 32; t++)
            acc += __expf(g_pm[bi * 32 + t] - M) *
                   g_pc[(size_t)(bi * 32 + t) * H_DIM + h];
        dout[bi * H_DIM + h] = acc * invL;
    }
#pragma unroll
    for (int k = 0; k < 2; k++) {
        int s = part * 512 + k * 256 + tid;
        dout[B_DIM * H_DIM + bi * S_DIM + s] =
            __expf(g_scores[bi * S_DIM + s] - M) * invL;
    }
}

// ---------------------------------------------------------------------------
extern "C" void kernel_launch(void* const* d_in, const int* in_sizes, int n_in,
                              void* d_out, int out_size) {
    const float* out_t  = (const float*)d_in[0];
    const float* hidden = (const float*)d_in[1];
    const float* W      = (const float*)d_in[2];
    const float* bvec   = (const float*)d_in[3];
    const float* v      = (const float*)d_in[4];
    int hid_off = in_sizes[1] - B_DIM * H_DIM;

    cudaFuncSetAttribute(attn_main_kernel,
                         cudaFuncAttributeMaxDynamicSharedMemorySize, SM_TOTAL);

    prep_kernel<<<512, 256>>>(W, bvec, hidden, hid_off);
    pad_kernel<<<1, 32>>>();
    pad_kernel<<<1, 32>>>();
    attn_main_kernel<<<NTILES, NT, SM_TOTAL>>>(out_t, v);
    finalize_kernel<<<B_DIM * 8, 256>>>((float*)d_out);
}